// round 7
// baseline (speedup 1.0000x reference)
#include <cuda_runtime.h>
#include <cstdint>

#define NN 8192u
#define MD 8193u
#define MM 67125249u           // 8193*8193
#define BIAS_START 67117056u   // 8192*8193 (start of last row within a matrix)
#define DIAG_STRIDE 8194u      // diag element i at i*(MD+1) within a matrix
#define CLCU 16384u            // 2*NN floats of cl/cu before the matrices
#define AL_START 16384u        // float offset of A_l
#define AU_START 67141633u     // CLCU + MM
#define EPS_ALPHA 1e-5f

struct Relax { float cl, cu, dl, du, bl, bu; };

__device__ __forceinline__ Relax relax(float l, float u)
{
    float den_ul = (u > l)    ? (u - l)    : 1.0f;
    float den_6l = (l < 6.0f) ? (6.0f - l) : 1.0f;
    float u_safe = (u > 0.0f) ? u          : 1.0f;

    bool mA = (u > 0.0f) && (u <= 6.0f) && (l >= 0.0f);
    bool mB = (u > 0.0f) && (u <= 6.0f) && (l <  0.0f);
    bool mC = (u > 6.0f) && (l <= 0.0f);
    bool mD = (u > 6.0f) && (l >  0.0f) && (l <= 6.0f);
    bool mE = (l > 6.0f);

    float alpha_B = (u < -l) ? EPS_ALPHA : 1.0f;
    float lam_B   = u / den_ul;
    float aU_C    = ((u - 6.0f) < (6.0f - l)) ? (6.0f / den_6l) : EPS_ALPHA;
    float aL_C    = (u < -l) ? EPS_ALPHA : (6.0f / u_safe);
    float aU_D    = ((u - 6.0f) < (6.0f - l)) ? 1.0f : EPS_ALPHA;
    float aL_D    = (6.0f - l) / den_ul;

    float fA = mA ? 1.0f : 0.0f;
    float fB = mB ? 1.0f : 0.0f;
    float fC = mC ? 1.0f : 0.0f;
    float fD = mD ? 1.0f : 0.0f;
    float fE = mE ? 1.0f : 0.0f;

    Relax r;
    r.du = fA * 1.0f + fB * lam_B   + fC * aU_C + fD * aU_D;
    r.dl = fA * 1.0f + fB * alpha_B + fC * aL_C + fD * aL_D;
    r.bu = fB * (-lam_B * l)
         + fC * (6.0f * (1.0f - aU_C))
         + fD * (6.0f * (1.0f - aU_D))
         + fE * 6.0f;
    r.bl = fD * (l * (1.0f - aL_D)) + fE * 6.0f;
    r.cu = fA * u + fB * u
         + fC * (6.0f + aU_C * (u - 6.0f))
         + fD * (6.0f + aU_D * (u - 6.0f))
         + fE * 6.0f;
    r.cl = fA * l + fB * (alpha_B * l) + fC * (aL_C * l)
         + fD * l + fE * 6.0f;
    return r;
}

// One store per thread. Thread index space:
//   [0, 16384)            : cl/cu scalar writes (coalesced)
//   [16384, 24576)        : A_l diagonal (i = t - 16384), scattered lines
//   [24576, 32768)        : A_u diagonal
//   [32768, 40960)        : A_l bias row (coalesced)
//   [40960, 49152)        : A_u bias row (coalesced)
//   49152                 : both corners
__global__ void relu6_fill(const float* __restrict__ lower,
                           const float* __restrict__ upper,
                           float* __restrict__ out)
{
    unsigned t = blockIdx.x * blockDim.x + threadIdx.x;
    if (t > 49152u) return;

    if (t == 49152u) {
        out[AL_START + BIAS_START + NN] = 1.0f;
        out[AU_START + BIAS_START + NN] = 1.0f;
        return;
    }

    unsigned seg = t >> 13;          // /8192
    unsigned i   = t & (NN - 1u);
    Relax r = relax(lower[i], upper[i]);

    switch (seg) {
    case 0: out[i] = r.cl; break;
    case 1: out[NN + i] = r.cu; break;
    case 2: out[AL_START + i * DIAG_STRIDE] = r.dl; break;
    case 3: out[AU_START + i * DIAG_STRIDE] = r.du; break;
    case 4: out[AL_START + BIAS_START + i] = r.bl; break;
    default: out[AU_START + BIAS_START + i] = r.bu; break;
    }
}

extern "C" void kernel_launch(void* const* d_in, const int* in_sizes, int n_in,
                              void* d_out, int out_size)
{
    const float* lower = (const float*)d_in[0];
    const float* upper = (const float*)d_in[1];
    float* out = (float*)d_out;

    // Zero both matrices (cl/cu region is fully written by the fill kernel).
    cudaMemsetAsync(out + AL_START, 0, (size_t)(2u * MM) * sizeof(float), 0);

    unsigned total_threads = 49153u;
    unsigned threads = 256u;
    unsigned blocks = (total_threads + threads - 1u) / threads;
    relu6_fill<<<blocks, threads>>>(lower, upper, out);
}

// round 8
// speedup vs baseline: 1.0175x; 1.0175x over previous
#include <cuda_runtime.h>
#include <cstdint>

#define NN 8192u
#define MD 8193u
#define MM 67125249u            // 8193*8193
#define BIAS_START 67117056u    // 8192*8193
#define DIAG_STRIDE 8194u
#define CLCU 16384u
#define AL_START 16384u         // float offset of A_l
#define AU_START 67141633u      // CLCU + MM (odd!)
#define AL_BIAS 67133440u       // AL_START + BIAS_START (mult of 8)
#define AU_BIAS_CHUNK0 134258688u // (AU_START + BIAS_START) - 1, mult of 8
#define TAIL 134266880u         // last two elements: bias_u[8191], corner
#define EPS_ALPHA 1e-5f

struct Relax { float cl, cu, dl, du, bl, bu; };

__device__ __forceinline__ Relax relax(float l, float u)
{
    float den_ul = (u > l)    ? (u - l)    : 1.0f;
    float den_6l = (l < 6.0f) ? (6.0f - l) : 1.0f;
    float u_safe = (u > 0.0f) ? u          : 1.0f;

    bool mA = (u > 0.0f) && (u <= 6.0f) && (l >= 0.0f);
    bool mB = (u > 0.0f) && (u <= 6.0f) && (l <  0.0f);
    bool mC = (u > 6.0f) && (l <= 0.0f);
    bool mD = (u > 6.0f) && (l >  0.0f) && (l <= 6.0f);
    bool mE = (l > 6.0f);

    float alpha_B = (u < -l) ? EPS_ALPHA : 1.0f;
    float lam_B   = u / den_ul;
    float aU_C    = ((u - 6.0f) < (6.0f - l)) ? (6.0f / den_6l) : EPS_ALPHA;
    float aL_C    = (u < -l) ? EPS_ALPHA : (6.0f / u_safe);
    float aU_D    = ((u - 6.0f) < (6.0f - l)) ? 1.0f : EPS_ALPHA;
    float aL_D    = (6.0f - l) / den_ul;

    float fA = mA ? 1.0f : 0.0f;
    float fB = mB ? 1.0f : 0.0f;
    float fC = mC ? 1.0f : 0.0f;
    float fD = mD ? 1.0f : 0.0f;
    float fE = mE ? 1.0f : 0.0f;

    Relax r;
    r.du = fA * 1.0f + fB * lam_B   + fC * aU_C + fD * aU_D;
    r.dl = fA * 1.0f + fB * alpha_B + fC * aL_C + fD * aL_D;
    r.bu = fB * (-lam_B * l)
         + fC * (6.0f * (1.0f - aU_C))
         + fD * (6.0f * (1.0f - aU_D))
         + fE * 6.0f;
    r.bl = fD * (l * (1.0f - aL_D)) + fE * 6.0f;
    r.cu = fA * u + fB * u
         + fC * (6.0f + aU_C * (u - 6.0f))
         + fD * (6.0f + aU_D * (u - 6.0f))
         + fE * 6.0f;
    r.cl = fA * l + fB * (alpha_B * l) + fC * (aL_C * l)
         + fD * l + fE * 6.0f;
    return r;
}

__device__ __forceinline__ void st256(float* p, const float v[8])
{
    asm volatile("st.global.v8.f32 [%0], {%1,%2,%3,%4,%5,%6,%7,%8};"
                 :: "l"(p),
                    "f"(v[0]), "f"(v[1]), "f"(v[2]), "f"(v[3]),
                    "f"(v[4]), "f"(v[5]), "f"(v[6]), "f"(v[7])
                 : "memory");
}

// All special values written as aligned full-sector (32B) v8 stores.
// Thread map:
//   [0, 2048)        cl/cu chunks (contiguous)
//   [2048, 10240)    A_l diagonal chunks (i = t-2048)
//   [10240, 18432)   A_u diagonal chunks (i=0 chunk also carries A_l corner)
//   [18432, 19456)   A_l bias row chunks (cols 0..8191)
//   [19456, 20480)   A_u bias row chunks (cols -1..8190)
//   20480            tail float2: bias_u[8191], corner(=1)
__global__ void relu6_fill_v8(const float* __restrict__ lower,
                              const float* __restrict__ upper,
                              float* __restrict__ out)
{
    unsigned t = blockIdx.x * blockDim.x + threadIdx.x;
    if (t > 20480u) return;

    if (t == 20480u) {
        Relax r = relax(lower[NN - 1u], upper[NN - 1u]);
        float2 w = make_float2(r.bu, 1.0f);
        asm volatile("st.global.v2.f32 [%0], {%1,%2};"
                     :: "l"(out + TAIL), "f"(w.x), "f"(w.y) : "memory");
        return;
    }

    float v[8];
    unsigned base;

    if (t < 2048u) {
        base = t * 8u;
        bool isCl = base < NN;
        #pragma unroll
        for (int j = 0; j < 8; ++j) {
            unsigned i = (base + j) & (NN - 1u);
            Relax r = relax(lower[i], upper[i]);
            v[j] = isCl ? r.cl : r.cu;
        }
    } else if (t < 10240u) {
        unsigned i = t - 2048u;
        unsigned e = AL_START + i * DIAG_STRIDE;
        base = e & ~7u;
        #pragma unroll
        for (int j = 0; j < 8; ++j) v[j] = 0.0f;
        Relax r = relax(lower[i], upper[i]);
        v[e - base] = r.dl;
    } else if (t < 18432u) {
        unsigned i = t - 10240u;
        unsigned e = AU_START + i * DIAG_STRIDE;
        base = e & ~7u;
        #pragma unroll
        for (int j = 0; j < 8; ++j) v[j] = 0.0f;
        Relax r = relax(lower[i], upper[i]);
        v[e - base] = r.du;
        if (i == 0u) v[0] = 1.0f;     // A_l corner lives at base+0 of this chunk
    } else if (t < 19456u) {
        unsigned k = t - 18432u;
        base = AL_BIAS + k * 8u;
        #pragma unroll
        for (int j = 0; j < 8; ++j) {
            unsigned c = (base - AL_BIAS) + j;        // 0..8191
            Relax r = relax(lower[c], upper[c]);
            v[j] = r.bl;
        }
    } else {
        unsigned k = t - 19456u;
        base = AU_BIAS_CHUNK0 + k * 8u;
        #pragma unroll
        for (int j = 0; j < 8; ++j) {
            int p = (int)(base + j) - (int)(AU_BIAS_CHUNK0 + 1u); // -1..8190
            if (p < 0) { v[j] = 0.0f; }
            else {
                Relax r = relax(lower[p], upper[p]);
                v[j] = r.bu;
            }
        }
    }

    st256(out + base, v);
}

extern "C" void kernel_launch(void* const* d_in, const int* in_sizes, int n_in,
                              void* d_out, int out_size)
{
    const float* lower = (const float*)d_in[0];
    const float* upper = (const float*)d_in[1];
    float* out = (float*)d_out;

    // Zero both matrices; cl/cu region written entirely by the fill kernel.
    cudaMemsetAsync(out + AL_START, 0, (size_t)(2u * MM) * sizeof(float), 0);

    unsigned total_threads = 20481u;
    unsigned threads = 256u;
    unsigned blocks = (total_threads + threads - 1u) / threads;
    relu6_fill_v8<<<blocks, threads>>>(lower, upper, out);
}